// round 2
// baseline (speedup 1.0000x reference)
#include <cuda_runtime.h>
#include <cstdint>

#define NB 16
#define NP 8192
#define NG 512
#define NK 32
#define TOK 384
#define NM (NB*NG)

typedef unsigned long long ull;

// scratch: centered group points [m][k][3]
__device__ float g_groups[NM * NK * 3];

// ---------- small helpers ----------
__device__ __forceinline__ ull packdup(float a) {
    ull d; asm("mov.b64 %0, {%1, %1};" : "=l"(d) : "f"(a)); return d;
}
__device__ __forceinline__ void fma2(ull& d, ull a, ull b) {
    asm("fma.rn.f32x2 %0, %1, %2, %0;" : "+l"(d) : "l"(a), "l"(b));
}
__device__ __forceinline__ float2 unpack2(ull d) {
    float2 r; asm("mov.b64 {%0, %1}, %2;" : "=f"(r.x), "=f"(r.y) : "l"(d)); return r;
}
__device__ __forceinline__ void atomicMaxF(float* a, float v) {
    if (v >= 0.f) atomicMax((int*)a, __float_as_int(v));
    else          atomicMin((unsigned int*)a, __float_as_uint(v));
}
#define NEG_INF __int_as_float(0xff800000)
#define POS_INF __int_as_float(0x7f800000)

// =====================================================================
// Kernel 1: farthest point sampling. 1 CTA per batch, 1024 threads,
// 8 points per thread held in registers. Writes centers to d_out region.
// =====================================================================
__global__ __launch_bounds__(1024) void fps_kernel(
    const float* __restrict__ pts, float* __restrict__ centers)
{
    int b = blockIdx.x;
    int t = threadIdx.x;
    const float* P = pts + (size_t)b * NP * 3;

    float px[8], py[8], pz[8], md[8];
#pragma unroll
    for (int j = 0; j < 8; j++) {
        int n = j * 1024 + t;
        px[j] = P[n*3+0]; py[j] = P[n*3+1]; pz[j] = P[n*3+2];
        md[j] = 1e10f;
    }

    __shared__ float s_val[32];
    __shared__ int   s_idx[32];
    __shared__ float s_c[3];
    __shared__ int   s_last;

    int last = 0;
    for (int s = 0; s < NG; s++) {
        if (t == 0) {
            float cx = P[last*3+0], cy = P[last*3+1], cz = P[last*3+2];
            s_c[0] = cx; s_c[1] = cy; s_c[2] = cz;
            float* C = centers + ((size_t)b * NG + s) * 3;
            C[0] = cx; C[1] = cy; C[2] = cz;
        }
        __syncthreads();
        float cx = s_c[0], cy = s_c[1], cz = s_c[2];

        float bv = NEG_INF; int bi = 0x7fffffff;
#pragma unroll
        for (int j = 0; j < 8; j++) {
            float dx = px[j] - cx, dy = py[j] - cy, dz = pz[j] - cz;
            float d2 = fmaf(dz, dz, fmaf(dy, dy, __fmul_rn(dx, dx)));
            md[j] = fminf(md[j], d2);
            int n = j * 1024 + t;
            if (md[j] > bv || (md[j] == bv && n < bi)) { bv = md[j]; bi = n; }
        }
        // warp argmax (max val, tie -> min idx)
#pragma unroll
        for (int off = 16; off; off >>= 1) {
            float ov = __shfl_down_sync(0xffffffffu, bv, off);
            int   oi = __shfl_down_sync(0xffffffffu, bi, off);
            if (ov > bv || (ov == bv && oi < bi)) { bv = ov; bi = oi; }
        }
        if ((t & 31) == 0) { s_val[t >> 5] = bv; s_idx[t >> 5] = bi; }
        __syncthreads();
        if (t < 32) {
            bv = s_val[t]; bi = s_idx[t];
#pragma unroll
            for (int off = 16; off; off >>= 1) {
                float ov = __shfl_down_sync(0xffffffffu, bv, off);
                int   oi = __shfl_down_sync(0xffffffffu, bi, off);
                if (ov > bv || (ov == bv && oi < bi)) { bv = ov; bi = oi; }
            }
            if (t == 0) s_last = bi;
        }
        __syncthreads();
        last = s_last;
    }
}

// =====================================================================
// Kernel 2: K=32 nearest neighbors per center + centered group gather.
// 1 CTA (256 thr) per center. d2 row in smem, 32 exact argmin passes
// (tie -> lowest index, matching lax.top_k). Order downstream is
// max-pooled, so only set membership matters.
// =====================================================================
__global__ __launch_bounds__(256) void group_kernel(
    const float* __restrict__ pts, const float* __restrict__ centers)
{
    __shared__ float d2s[NP];
    __shared__ float rv[8];
    __shared__ int   ri[8];
    __shared__ int   sel[NK];

    int m = blockIdx.x;
    int b = m >> 9;           // NG = 512
    int t = threadIdx.x;
    const float* P = pts + (size_t)b * NP * 3;

    float cx = centers[m*3+0], cy = centers[m*3+1], cz = centers[m*3+2];
    float cn = fmaf(cz, cz, fmaf(cy, cy, __fmul_rn(cx, cx)));

#pragma unroll 4
    for (int j = 0; j < 32; j++) {
        int n = j * 256 + t;
        float x = P[n*3+0], y = P[n*3+1], z = P[n*3+2];
        float pn  = fmaf(z, z, fmaf(y, y, __fmul_rn(x, x)));
        float dot = fmaf(cz, z, fmaf(cy, y, __fmul_rn(cx, x)));
        d2s[n] = __fadd_rn(cn, pn) - 2.0f * dot;
    }
    __syncthreads();

    for (int p = 0; p < NK; p++) {
        float bv = POS_INF; int bi = 0x7fffffff;
#pragma unroll
        for (int j = 0; j < 32; j++) {
            int n = j * 256 + t;
            float v = d2s[n];
            if (v < bv || (v == bv && n < bi)) { bv = v; bi = n; }
        }
#pragma unroll
        for (int off = 16; off; off >>= 1) {
            float ov = __shfl_down_sync(0xffffffffu, bv, off);
            int   oi = __shfl_down_sync(0xffffffffu, bi, off);
            if (ov < bv || (ov == bv && oi < bi)) { bv = ov; bi = oi; }
        }
        if ((t & 31) == 0) { rv[t >> 5] = bv; ri[t >> 5] = bi; }
        __syncthreads();
        if (t == 0) {
            float fv = rv[0]; int fi = ri[0];
#pragma unroll
            for (int w = 1; w < 8; w++)
                if (rv[w] < fv || (rv[w] == fv && ri[w] < fi)) { fv = rv[w]; fi = ri[w]; }
            sel[p] = fi;
            d2s[fi] = POS_INF;
        }
        __syncthreads();
    }

    if (t < NK * 3) {
        int k = t / 3, c = t % 3;
        int n = sel[k];
        g_groups[((size_t)m * NK + k) * 3 + c] = P[n*3+c] - centers[m*3+c];
    }
}

// =====================================================================
// Kernel 3: fused MLP per group. 1 CTA (256 thr) per group (32 rows).
// All activations in smem, weights streamed through a smem tile with
// register prefetch. GEMM micro-tile: 4 rows x 4 cols per thread using
// packed fma.rn.f32x2 (2 fp32 FMA / issue).
//   stage1: 3->128 (+bn1,relu)       in smem F1[c][k]
//   stage2: 128->256 (+b2), max->g   in smem F2[c][k], GM[256]
//   stage3: concat(512)->512: g-part k<256 is row-constant (flop saving),
//           f2-part k>=256 full GEMM; +bn2,relu -> F3[c][k]
//   stage4: 512->384 (+b4), max over k -> token[384]
// =====================================================================
__device__ __forceinline__ void ldg_tile(float4* r, const float* __restrict__ W,
                                         int Kdim, int cb, int k0, int t) {
#pragma unroll
    for (int i = 0; i < 4; i++) {
        int f = t + i * 256;
        int c = f >> 3, kq = f & 7;
        r[i] = *(const float4*)(W + (size_t)(cb + c) * Kdim + k0 + kq * 4);
    }
}
__device__ __forceinline__ void sts_tile(float* __restrict__ WT, const float4* r, int t) {
#pragma unroll
    for (int i = 0; i < 4; i++) {
        int f = t + i * 256;
        int c = f >> 3, kq = f & 7;
        WT[(kq*4+0)*128 + c] = r[i].x;
        WT[(kq*4+1)*128 + c] = r[i].y;
        WT[(kq*4+2)*128 + c] = r[i].z;
        WT[(kq*4+3)*128 + c] = r[i].w;
    }
}
__device__ __forceinline__ void mma_tile(ull acc[4][2], const float* __restrict__ A,
                                         const float* __restrict__ WT, int rt, int cc) {
#pragma unroll
    for (int kk = 0; kk < 32; kk++) {
        float4 a = *(const float4*)(A + kk*32 + rt*4);
        ulonglong2 bp = *(const ulonglong2*)(WT + kk*128 + cc);
        ull a0 = packdup(a.x), a1 = packdup(a.y), a2 = packdup(a.z), a3 = packdup(a.w);
        fma2(acc[0][0], a0, bp.x); fma2(acc[0][1], a0, bp.y);
        fma2(acc[1][0], a1, bp.x); fma2(acc[1][1], a1, bp.y);
        fma2(acc[2][0], a2, bp.x); fma2(acc[2][1], a2, bp.y);
        fma2(acc[3][0], a3, bp.x); fma2(acc[3][1], a3, bp.y);
    }
}

#define SMEM_FLOATS 33504
#define SMEM_BYTES  (SMEM_FLOATS * 4)

__global__ __launch_bounds__(256, 1) void mlp_kernel(
    const float* __restrict__ w1,
    const float* __restrict__ bn1g, const float* __restrict__ bn1b,
    const float* __restrict__ bn1m, const float* __restrict__ bn1v,
    const float* __restrict__ w2,  const float* __restrict__ b2,
    const float* __restrict__ w3,
    const float* __restrict__ bn2g, const float* __restrict__ bn2b,
    const float* __restrict__ bn2m, const float* __restrict__ bn2v,
    const float* __restrict__ w4,  const float* __restrict__ b4,
    float* __restrict__ tokens)
{
    extern __shared__ float sm[];
    float* F1  = sm;           // [128][32]
    float* F2  = sm + 4096;    // [256][32]
    float* F3  = sm + 12288;   // [512][32]
    float* WT  = sm + 28672;   // [32][128] weight tile
    float* GM  = sm + 32768;   // [256] group max of f2
    float* TK  = sm + 33024;   // [384] token accum
    float* PTS = sm + 33408;   // [32*3]

    int m = blockIdx.x;
    int t = threadIdx.x;
    int rt = t >> 5;           // row-thread 0..7 -> rows 4rt..4rt+3
    int cc = (t & 31) * 4;     // col offset within 128-col tile

    if (t < NK * 3) PTS[t] = g_groups[(size_t)m * (NK*3) + t];
    GM[t] = NEG_INF;
    if (t < 256) TK[t] = NEG_INF;   // note: t always < 256
    if (t < TOK - 256) TK[256 + t] = NEG_INF;
    __syncthreads();

    // ---- stage 1: 3 -> 128, bn1 + relu ----
    {
        int c  = t >> 1;
        int k0 = (t & 1) * 16;
        float wx = w1[c*3+0], wy = w1[c*3+1], wz = w1[c*3+2];
        float sc = bn1g[c] * rsqrtf(bn1v[c] + 1e-5f);
        float sh = fmaf(-bn1m[c], sc, bn1b[c]);
#pragma unroll
        for (int kk = 0; kk < 16; kk++) {
            int k = k0 + kk;
            float v = fmaf(PTS[k*3+2], wz, fmaf(PTS[k*3+1], wy, PTS[k*3+0] * wx));
            F1[c*32 + k] = fmaxf(fmaf(v, sc, sh), 0.f);
        }
    }

    // ---- stage 2: 128 -> 256, +b2 ; max over rows -> GM ----
    for (int ct = 0; ct < 2; ct++) {
        int cb = ct * 128;
        ull acc[4][2] = {};
        float4 pf[4];
        ldg_tile(pf, w2, 128, cb, 0, t);
        for (int kt = 0; kt < 4; kt++) {
            __syncthreads();
            sts_tile(WT, pf, t);
            __syncthreads();
            if (kt < 3) ldg_tile(pf, w2, 128, cb, (kt+1)*32, t);
            mma_tile(acc, F1 + kt*1024, WT, rt, cc);
        }
#pragma unroll
        for (int j = 0; j < 2; j++) {
            int c0 = cb + cc + 2*j;
            float bb0 = b2[c0], bb1 = b2[c0+1];
            float m0 = NEG_INF, m1 = NEG_INF;
#pragma unroll
            for (int i = 0; i < 4; i++) {
                float2 v = unpack2(acc[i][j]);
                v.x += bb0; v.y += bb1;
                F2[(c0  )*32 + rt*4 + i] = v.x;
                F2[(c0+1)*32 + rt*4 + i] = v.y;
                m0 = fmaxf(m0, v.x); m1 = fmaxf(m1, v.y);
            }
            atomicMaxF(&GM[c0], m0);
            atomicMaxF(&GM[c0+1], m1);
        }
    }

    // ---- stage 3: concat(512) -> 512, bn2 + relu ----
    for (int ct = 0; ct < 4; ct++) {
        int cb = ct * 128;
        ull acc[4][2] = {};
        ull gs[2] = {};
        float4 pf[4];
        ldg_tile(pf, w3, 512, cb, 0, t);
        for (int kt = 0; kt < 16; kt++) {
            __syncthreads();
            sts_tile(WT, pf, t);
            __syncthreads();
            if (kt < 15) ldg_tile(pf, w3, 512, cb, (kt+1)*32, t);
            if (kt < 8) {   // g half of concat: row-constant
#pragma unroll
                for (int kk = 0; kk < 32; kk++) {
                    ull gd = packdup(GM[kt*32 + kk]);
                    ulonglong2 bp = *(const ulonglong2*)(WT + kk*128 + cc);
                    fma2(gs[0], gd, bp.x); fma2(gs[1], gd, bp.y);
                }
            } else {        // f2 half
                mma_tile(acc, F2 + (kt-8)*1024, WT, rt, cc);
            }
        }
#pragma unroll
        for (int j = 0; j < 2; j++) {
            int c0 = cb + cc + 2*j;
            float2 gp = unpack2(gs[j]);
            float sc0 = bn2g[c0  ] * rsqrtf(bn2v[c0  ] + 1e-5f);
            float sh0 = fmaf(-bn2m[c0  ], sc0, bn2b[c0  ]);
            float sc1 = bn2g[c0+1] * rsqrtf(bn2v[c0+1] + 1e-5f);
            float sh1 = fmaf(-bn2m[c0+1], sc1, bn2b[c0+1]);
#pragma unroll
            for (int i = 0; i < 4; i++) {
                float2 v = unpack2(acc[i][j]);
                float x0 = v.x + gp.x, x1 = v.y + gp.y;
                F3[(c0  )*32 + rt*4 + i] = fmaxf(fmaf(x0, sc0, sh0), 0.f);
                F3[(c0+1)*32 + rt*4 + i] = fmaxf(fmaf(x1, sc1, sh1), 0.f);
            }
        }
    }

    // ---- stage 4: 512 -> 384, +b4 ; max over rows -> TK ----
    for (int ct = 0; ct < 3; ct++) {
        int cb = ct * 128;
        ull acc[4][2] = {};
        float4 pf[4];
        ldg_tile(pf, w4, 512, cb, 0, t);
        for (int kt = 0; kt < 16; kt++) {
            __syncthreads();
            sts_tile(WT, pf, t);
            __syncthreads();
            if (kt < 15) ldg_tile(pf, w4, 512, cb, (kt+1)*32, t);
            mma_tile(acc, F3 + kt*1024, WT, rt, cc);
        }
#pragma unroll
        for (int j = 0; j < 2; j++) {
            int c0 = cb + cc + 2*j;
            float bb0 = b4[c0], bb1 = b4[c0+1];
            float m0 = NEG_INF, m1 = NEG_INF;
#pragma unroll
            for (int i = 0; i < 4; i++) {
                float2 v = unpack2(acc[i][j]);
                m0 = fmaxf(m0, v.x + bb0);
                m1 = fmaxf(m1, v.y + bb1);
            }
            atomicMaxF(&TK[c0], m0);
            atomicMaxF(&TK[c0+1], m1);
        }
    }
    __syncthreads();

    tokens[(size_t)m * TOK + t] = TK[t];
    if (t < TOK - 256) tokens[(size_t)m * TOK + 256 + t] = TK[256 + t];
}

// =====================================================================
extern "C" void kernel_launch(void* const* d_in, const int* in_sizes, int n_in,
                              void* d_out, int out_size)
{
    const float* points = (const float*)d_in[0];
    const float* w1     = (const float*)d_in[1];
    const float* bn1g   = (const float*)d_in[2];
    const float* bn1b   = (const float*)d_in[3];
    const float* bn1m   = (const float*)d_in[4];
    const float* bn1v   = (const float*)d_in[5];
    const float* w2     = (const float*)d_in[6];
    const float* b2     = (const float*)d_in[7];
    const float* w3     = (const float*)d_in[8];
    const float* bn2g   = (const float*)d_in[9];
    const float* bn2b   = (const float*)d_in[10];
    const float* bn2m   = (const float*)d_in[11];
    const float* bn2v   = (const float*)d_in[12];
    const float* w4     = (const float*)d_in[13];
    const float* b4     = (const float*)d_in[14];

    float* tokens  = (float*)d_out;                      // [B,G,384]
    float* centers = (float*)d_out + (size_t)NM * TOK;   // [B,G,3]

    fps_kernel<<<NB, 1024>>>(points, centers);
    group_kernel<<<NM, 256>>>(points, centers);

    cudaFuncSetAttribute(mlp_kernel, cudaFuncAttributeMaxDynamicSharedMemorySize, SMEM_BYTES);
    mlp_kernel<<<NM, 256, SMEM_BYTES>>>(w1, bn1g, bn1b, bn1m, bn1v,
                                        w2, b2, w3,
                                        bn2g, bn2b, bn2m, bn2v,
                                        w4, b4, tokens);
}